// round 16
// baseline (speedup 1.0000x reference)
#include <cuda_runtime.h>
#include <cuda_fp16.h>

#define Dm 128
#define Hm 256
#define ROWS 16384   /* 16 * 1024 chunks */
#define NTOK 131072  /* 16 * 8192 tokens */
#define EPSf 1e-5f

typedef unsigned long long u64;
typedef unsigned int u32;

// ---- scratch (device globals; no allocation) ----
__device__ __half g_localh[NTOK * Dm]; // 32 MB (fp16 local)
__device__ float g_hA[ROWS * Dm];      // 8 MB
__device__ float g_hB[ROWS * Dm];      // 8 MB
__device__ float g_bcb[ROWS * Dm];     // 8 MB
// fp16 weight fragments (m16n8k16 B layout)
__device__ uint2 g_w1h[8 * 32 * 32];   // lw1 128x256
__device__ uint2 g_w2h[16 * 16 * 32];  // lw2 256x128
__device__ uint2 g_hwh[8 * 32 * 32];   // head_w 128x256
// fp16 128x128 msg mats: [0]=w1self [1]=w1nbr [2]=mw2 [3]=uw1a [4]=uw1b [5]=uw2 [6]=bc_w
__device__ uint2 g_mwh[7 * 4096];

// ---- packed f32x2 helpers (pool path) ----
__device__ __forceinline__ u64 pk2(float x, float y) {
    u64 r; asm("mov.b64 %0, {%1, %2};" : "=l"(r) : "f"(x), "f"(y)); return r;
}
__device__ __forceinline__ u64 dup_f(float a) {
    u64 r; asm("mov.b64 %0, {%1, %1};" : "=l"(r) : "f"(a)); return r;
}
__device__ __forceinline__ void fma2(u64& d, u64 a, u64 b) {
    asm("fma.rn.f32x2 %0, %1, %2, %0;" : "+l"(d) : "l"(a), "l"(b));
}
__device__ __forceinline__ float2 u2f(u64 v) {
    float2 r; asm("mov.b64 {%0, %1}, %2;" : "=f"(r.x), "=f"(r.y) : "l"(v)); return r;
}

// ---- fp16 helpers ----
__device__ __forceinline__ u32 h2u(float x, float y) {
    __half2 h = __floats2half2_rn(x, y);
    return *(u32*)&h;
}
__device__ __forceinline__ float2 uh2f(u32 v) {
    return __half22float2(*(__half2*)&v);
}

// mma.sync m16n8k16 f16 (fp32 accum)
__device__ __forceinline__ void mma16(float4& c, const u32 a[4], u32 b0, u32 b1) {
    asm volatile(
        "mma.sync.aligned.m16n8k16.row.col.f32.f16.f16.f32 "
        "{%0,%1,%2,%3}, {%4,%5,%6,%7}, {%8,%9}, {%0,%1,%2,%3};"
        : "+f"(c.x), "+f"(c.y), "+f"(c.z), "+f"(c.w)
        : "r"(a[0]), "r"(a[1]), "r"(a[2]), "r"(a[3]), "r"(b0), "r"(b1));
}

// fp16 A fragment: ap pre-offset to (row, ks*16 + 2*fcol), stride in halves
template<int STRIDE>
__device__ __forceinline__ void ldA_h(const __half* ap, u32 a[4]) {
    a[0] = *(const u32*)(ap);
    a[1] = *(const u32*)(ap + 8 * STRIDE);
    a[2] = *(const u32*)(ap + 8);
    a[3] = *(const u32*)(ap + 8 * STRIDE + 8);
}

__device__ __forceinline__ float wsum(float v) {
#pragma unroll
    for (int o = 16; o; o >>= 1) v += __shfl_xor_sync(0xffffffffu, v, o);
    return v;
}
__device__ __forceinline__ float gelu_f(float x) {
    return 0.5f * x * (1.0f + erff(x * 0.70710678118f));
}

__device__ __forceinline__ float4 ln_f4(float4 h, const float* __restrict__ g,
                                        const float* __restrict__ b, int lane) {
    const float mu = wsum(h.x + h.y + h.z + h.w) * (1.0f / 128.0f);
    const float a0 = h.x - mu, a1 = h.y - mu, a2 = h.z - mu, a3 = h.w - mu;
    const float var = wsum(a0 * a0 + a1 * a1 + a2 * a2 + a3 * a3) * (1.0f / 128.0f);
    const float rs = rsqrtf(var + EPSf);
    const int dd = lane * 4;
    const float4 gg = *(const float4*)(g + dd);
    const float4 bb = *(const float4*)(b + dd);
    return make_float4(a0 * rs * gg.x + bb.x, a1 * rs * gg.y + bb.y,
                       a2 * rs * gg.z + bb.z, a3 * rs * gg.w + bb.w);
}

// ---- scalar register-tiled GEMM accumulate (pool only) ----
template<int KDIM, int RPT, int NCP>
__device__ __forceinline__ void mm_acc(const float* __restrict__ s,
                                       const float* __restrict__ W, const int ldw,
                                       u64 acc[RPT][NCP]) {
#pragma unroll 2
    for (int d = 0; d < KDIM; d += 2) {
        u64 w0[NCP], w1[NCP];
        if constexpr (NCP >= 2) {
#pragma unroll
            for (int c = 0; c < NCP; c += 2) {
                const ulonglong2 t0 = *(const ulonglong2*)(W + d * ldw + c * 2);
                const ulonglong2 t1 = *(const ulonglong2*)(W + (d + 1) * ldw + c * 2);
                w0[c] = t0.x; w0[c + 1] = t0.y;
                w1[c] = t1.x; w1[c + 1] = t1.y;
            }
        } else {
            w0[0] = *(const u64*)(W + d * ldw);
            w1[0] = *(const u64*)(W + (d + 1) * ldw);
        }
#pragma unroll
        for (int r = 0; r < RPT; ++r) {
            const float2 a = *(const float2*)(s + r * KDIM + d);
            const u64 a0 = dup_f(a.x), a1 = dup_f(a.y);
#pragma unroll
            for (int c = 0; c < NCP; ++c) {
                fma2(acc[r][c], a0, w0[c]);
                fma2(acc[r][c], a1, w1[c]);
            }
        }
    }
}

// ============================================================
// K0: fused pack — everything to fp16 m16n8k16 B-fragments
// ============================================================
__device__ __forceinline__ void pack_one_h(const float* __restrict__ W,
                                           uint2* __restrict__ P,
                                           int N, int idx) {
    const int lane = idx & 31;
    const int t = idx >> 5;
    const int nt = t % (N / 8);
    const int ks = t / (N / 8);
    const int k0 = ks * 16 + 2 * (lane & 3);
    const int n = nt * 8 + (lane >> 2);
    uint2 r;
    r.x = h2u(W[k0 * N + n],       W[(k0 + 1) * N + n]);
    r.y = h2u(W[(k0 + 8) * N + n], W[(k0 + 9) * N + n]);
    P[idx] = r;
}

__global__ __launch_bounds__(256) void k_pack_all(
    const float* __restrict__ lw1, const float* __restrict__ lw2,
    const float* __restrict__ hw,  const float* __restrict__ mw1,
    const float* __restrict__ mw2, const float* __restrict__ uw1,
    const float* __restrict__ uw2, const float* __restrict__ bcw)
{
    const int b = blockIdx.x, tid = threadIdx.x;
    if      (b < 32)  pack_one_h(lw1, g_w1h, 256, b * 256 + tid);
    else if (b < 64)  pack_one_h(lw2, g_w2h, 128, (b - 32) * 256 + tid);
    else if (b < 96)  pack_one_h(hw,  g_hwh, 256, (b - 64) * 256 + tid);
    else if (b < 112) pack_one_h(mw1,           g_mwh + 0 * 4096, 128, (b - 96)  * 256 + tid);
    else if (b < 128) pack_one_h(mw1 + 16384,   g_mwh + 1 * 4096, 128, (b - 112) * 256 + tid);
    else if (b < 144) pack_one_h(mw2,           g_mwh + 2 * 4096, 128, (b - 128) * 256 + tid);
    else if (b < 160) pack_one_h(uw1,           g_mwh + 3 * 4096, 128, (b - 144) * 256 + tid);
    else if (b < 176) pack_one_h(uw1 + 16384,   g_mwh + 4 * 4096, 128, (b - 160) * 256 + tid);
    else if (b < 192) pack_one_h(uw2,           g_mwh + 5 * 4096, 128, (b - 176) * 256 + tid);
    else              pack_one_h(bcw,           g_mwh + 6 * 4096, 128, (b - 192) * 256 + tid);
}

// ============================================================
// K1: local = h + MLP2(LN(h)) + fused pool/summ  (fp16 MMA)
// 64 tokens/block, 256 threads, ~50KB smem, 3 CTAs/SM
// ============================================================
#define SXL 132   /* float stride */
#define SXH 136   /* half stride */
#define SHH 264   /* half stride for hidden */
__global__ __launch_bounds__(256, 3) void k_local(
    const int* __restrict__ x, const float* __restrict__ emb, const float* __restrict__ pos,
    const float* __restrict__ lb1, const float* __restrict__ lb2,
    const float* __restrict__ lng, const float* __restrict__ lnb,
    const float* __restrict__ pw, const float* __restrict__ pb)
{
    extern __shared__ char smc[];
    __half* s_x = (__half*)smc;                    // 64 x 136 halves
    __half* s_h = (__half*)(smc + 64 * SXH * 2);   // 64 x 264 halves
    const int tid = threadIdx.x, wid = tid >> 5, lane = tid & 31;
    const int gt0 = blockIdx.x * 64;
    const int frow = lane >> 2, fcol = lane & 3;

    // phase 1: LN per token -> fp16
#pragma unroll
    for (int tt = 0; tt < 8; ++tt) {
        const int tl = wid * 8 + tt, gt = gt0 + tl;
        const int xt = __ldg(x + gt);
        const float4 e = *(const float4*)(emb + xt * Dm + lane * 4);
        const float4 p = *(const float4*)(pos + (gt & 7) * Dm + lane * 4);
        const float4 h = make_float4(e.x + p.x, e.y + p.y, e.z + p.z, e.w + p.w);
        const float4 v = ln_f4(h, lng, lnb, lane);
        u32* dst = (u32*)(s_x + tl * SXH) + lane * 2;
        dst[0] = h2u(v.x, v.y);
        dst[1] = h2u(v.z, v.w);
    }
    __syncthreads();

    const int mg = (wid >> 2) * 32;
    const int ng = (wid & 3);

    // phase 2: hid = gelu(xln @ lw1 + b1)
    {
        float4 acc[2][8];
#pragma unroll
        for (int nt = 0; nt < 8; ++nt) {
            const int gc = ng * 64 + nt * 8 + 2 * fcol;
            const float b0 = lb1[gc], b1v = lb1[gc + 1];
#pragma unroll
            for (int mt = 0; mt < 2; ++mt) acc[mt][nt] = make_float4(b0, b1v, b0, b1v);
        }
#pragma unroll
        for (int ks = 0; ks < 8; ++ks) {
            u32 a[2][4];
#pragma unroll
            for (int mt = 0; mt < 2; ++mt)
                ldA_h<SXH>(s_x + (mg + mt * 16 + frow) * SXH + ks * 16 + 2 * fcol, a[mt]);
#pragma unroll
            for (int nt = 0; nt < 8; ++nt) {
                const uint2 b = g_w1h[(ks * 32 + ng * 8 + nt) * 32 + lane];
#pragma unroll
                for (int mt = 0; mt < 2; ++mt)
                    mma16(acc[mt][nt], a[mt], b.x, b.y);
            }
        }
#pragma unroll
        for (int mt = 0; mt < 2; ++mt) {
            const int rg = mg + mt * 16 + frow;
#pragma unroll
            for (int nt = 0; nt < 8; ++nt) {
                const int gc = ng * 64 + nt * 8 + 2 * fcol;
                *(u32*)(s_h + rg * SHH + gc) =
                    h2u(gelu_f(acc[mt][nt].x), gelu_f(acc[mt][nt].y));
                *(u32*)(s_h + (rg + 8) * SHH + gc) =
                    h2u(gelu_f(acc[mt][nt].z), gelu_f(acc[mt][nt].w));
            }
        }
    }
    __syncthreads();

    // phase 3: local = h + hid @ lw2 + b2 -> g_localh (fp16) and s_x (fp16)
    {
        float4 acc[2][4];
#pragma unroll
        for (int nt = 0; nt < 4; ++nt) {
            const int gc = ng * 32 + nt * 8 + 2 * fcol;
            const float b0 = lb2[gc], b1v = lb2[gc + 1];
#pragma unroll
            for (int mt = 0; mt < 2; ++mt) acc[mt][nt] = make_float4(b0, b1v, b0, b1v);
        }
#pragma unroll 4
        for (int ks = 0; ks < 16; ++ks) {
            u32 a[2][4];
#pragma unroll
            for (int mt = 0; mt < 2; ++mt)
                ldA_h<SHH>(s_h + (mg + mt * 16 + frow) * SHH + ks * 16 + 2 * fcol, a[mt]);
#pragma unroll
            for (int nt = 0; nt < 4; ++nt) {
                const uint2 b = g_w2h[(ks * 16 + ng * 4 + nt) * 32 + lane];
#pragma unroll
                for (int mt = 0; mt < 2; ++mt)
                    mma16(acc[mt][nt], a[mt], b.x, b.y);
            }
        }
#pragma unroll
        for (int mt = 0; mt < 2; ++mt) {
#pragma unroll
            for (int rr = 0; rr < 2; ++rr) {
                const int tl = mg + mt * 16 + frow + rr * 8;
                const int gt = gt0 + tl;
                const int xt = __ldg(x + gt);
#pragma unroll
                for (int nt = 0; nt < 4; ++nt) {
                    const int gc = ng * 32 + nt * 8 + 2 * fcol;
                    const float2 e = *(const float2*)(emb + xt * Dm + gc);
                    const float2 p = *(const float2*)(pos + (gt & 7) * Dm + gc);
                    const float cx = rr ? acc[mt][nt].z : acc[mt][nt].x;
                    const float cy = rr ? acc[mt][nt].w : acc[mt][nt].y;
                    const u32 oh = h2u(e.x + p.x + cx, e.y + p.y + cy);
                    *(u32*)(g_localh + gt * Dm + gc) = oh;
                    *(u32*)(s_x + tl * SXH + gc) = oh;
                }
            }
        }
    }
    __syncthreads();

    // phase 4: chunk means -> (float*)s_h[0:1024]
    float* s_m = (float*)s_h;
#pragma unroll
    for (int it = 0; it < 4; ++it) {
        const int idx = tid + it * 256;
        const int c = idx >> 7, dd = idx & 127;
        float s = 0.f;
#pragma unroll
        for (int t = 0; t < 8; ++t) s += __half2float(s_x[(c * 8 + t) * SXH + dd]);
        s_m[c * 128 + dd] = s * 0.125f;
    }
    __syncthreads();

    // phase 5: summ = mean @ pool_w + pool_b -> g_hA
    {
        const int j0 = lane * 4;
        u64 acc1[1][2];
        acc1[0][0] = pk2(pb[j0], pb[j0 + 1]);
        acc1[0][1] = pk2(pb[j0 + 2], pb[j0 + 3]);
        mm_acc<128, 1, 2>(s_m + wid * 128, pw + j0, 128, acc1);
        const float2 v0 = u2f(acc1[0][0]), v1 = u2f(acc1[0][1]);
        *(float4*)(g_hA + (blockIdx.x * 8 + wid) * Dm + j0) =
            make_float4(v0.x, v0.y, v1.x, v1.y);
    }
}

// ============================================================
// K2: FUSED msg round — fp16 MMA, fp32 residual from gmem
// (unchanged from 327us best)
// ============================================================
__global__ __launch_bounds__(256, 3) void k_msgf(
    int useA, int last,
    const float* __restrict__ mb1, const float* __restrict__ mb2,
    const float* __restrict__ ub1, const float* __restrict__ ub2,
    const float* __restrict__ lg, const float* __restrict__ lb,
    const float* __restrict__ bcb)
{
    const float* __restrict__ hin = useA ? g_hA : g_hB;
    float* __restrict__ hout = useA ? g_hB : g_hA;
    extern __shared__ char smc[];
    __half* s_hmtH = (__half*)smc;            // 36 rows
    __half* s_pnH  = s_hmtH + 36 * SXH;       // 36 rows
    __half* s_psH  = s_hmtH + 72 * SXH;       // 32 rows
    __half* s_hsH  = s_hmtH + 104 * SXH;      // 32 rows
    float*  s_pl   = (float*)(smc + 136 * SXH * 2);  // 32 x SXL fp32
    __half* s_agH  = s_pnH;
    __half* s_uhH  = s_psH;
    const int tid = threadIdx.x, wid = tid >> 5, lane = tid & 31;
    const int r0 = blockIdx.x * 32;
    const int frow = lane >> 2, fcol = lane & 3;
    const int ng = wid & 3;
    const int mgrp = wid >> 2;
    const int mrow = mgrp * 16;

    // P0
#pragma unroll
    for (int it = 0; it < 9; ++it) {
        const int idx = tid + it * 256;
        const int v = idx >> 6, jp = idx & 63;
        int row = r0 - 4 + v;
        row = row < 0 ? 0 : (row > ROWS - 1 ? ROWS - 1 : row);
        const float2 hv = *(const float2*)(hin + row * Dm + jp * 2);
        *((u32*)(s_hmtH + v * SXH) + jp) = h2u(hv.x, hv.y);
    }
    __syncthreads();

    // P1
    if (mgrp == 0) {
        float4 acc[2][4];
#pragma unroll
        for (int mt = 0; mt < 2; ++mt)
#pragma unroll
            for (int nt = 0; nt < 4; ++nt) acc[mt][nt] = make_float4(0.f, 0.f, 0.f, 0.f);
#pragma unroll
        for (int ks = 0; ks < 8; ++ks) {
            u32 a[2][4];
#pragma unroll
            for (int mt = 0; mt < 2; ++mt)
                ldA_h<SXH>(s_hmtH + (4 + mt * 16 + frow) * SXH + ks * 16 + 2 * fcol, a[mt]);
#pragma unroll
            for (int nt = 0; nt < 4; ++nt) {
                const uint2 b = g_mwh[0 * 4096 + (ks * 16 + ng * 4 + nt) * 32 + lane];
#pragma unroll
                for (int mt = 0; mt < 2; ++mt)
                    mma16(acc[mt][nt], a[mt], b.x, b.y);
            }
        }
#pragma unroll
        for (int mt = 0; mt < 2; ++mt) {
            const int r = mt * 16 + frow;
#pragma unroll
            for (int nt = 0; nt < 4; ++nt) {
                const int gc = ng * 32 + nt * 8 + 2 * fcol;
                *(u32*)(s_psH + r * SXH + gc)       = h2u(acc[mt][nt].x, acc[mt][nt].y);
                *(u32*)(s_psH + (r + 8) * SXH + gc) = h2u(acc[mt][nt].z, acc[mt][nt].w);
            }
        }
    } else {
        float4 acc[3][4];
#pragma unroll
        for (int mt = 0; mt < 3; ++mt)
#pragma unroll
            for (int nt = 0; nt < 4; ++nt) acc[mt][nt] = make_float4(0.f, 0.f, 0.f, 0.f);
        const int vb[3] = {0, 16, 20};
#pragma unroll
        for (int ks = 0; ks < 8; ++ks) {
            u32 a[3][4];
#pragma unroll
            for (int mt = 0; mt < 3; ++mt)
                ldA_h<SXH>(s_hmtH + (vb[mt] + frow) * SXH + ks * 16 + 2 * fcol, a[mt]);
#pragma unroll
            for (int nt = 0; nt < 4; ++nt) {
                const uint2 b = g_mwh[1 * 4096 + (ks * 16 + ng * 4 + nt) * 32 + lane];
#pragma unroll
                for (int mt = 0; mt < 3; ++mt)
                    mma16(acc[mt][nt], a[mt], b.x, b.y);
            }
        }
#pragma unroll
        for (int mt = 0; mt < 3; ++mt) {
            const int v = vb[mt] + frow;
#pragma unroll
            for (int nt = 0; nt < 4; ++nt) {
                const int gc = ng * 32 + nt * 8 + 2 * fcol;
                *(u32*)(s_pnH + v * SXH + gc)       = h2u(acc[mt][nt].x, acc[mt][nt].y);
                *(u32*)(s_pnH + (v + 8) * SXH + gc) = h2u(acc[mt][nt].z, acc[mt][nt].w);
            }
        }
    }
    __syncthreads();

    // P2: gelu-sum
#pragma unroll
    for (int it = 0; it < 8; ++it) {
        const int idx = tid + it * 256;
        const int r = idx >> 6, jp = idx & 63;
        const int i = (r0 + r) & 1023;
        const float2 b1v = *(const float2*)(mb1 + jp * 2);
        float2 ps = uh2f(*((const u32*)(s_psH + r * SXH) + jp));
        ps.x += b1v.x; ps.y += b1v.y;
        float a0 = 0.f, a1 = 0.f;
#pragma unroll
        for (int dd = 0; dd < 5; ++dd) {
            if (i >= dd) {
                const float2 pn = uh2f(*((const u32*)(s_pnH + (r + 4 - dd) * SXH) + jp));
                a0 += gelu_f(ps.x + pn.x);
                a1 += gelu_f(ps.y + pn.y);
            }
        }
        *((u32*)(s_hsH + r * SXH) + jp) = h2u(a0, a1);
    }
    __syncthreads();

    // P3: agg
    {
        float4 acc[4];
#pragma unroll
        for (int nt = 0; nt < 4; ++nt) acc[nt] = make_float4(0.f, 0.f, 0.f, 0.f);
#pragma unroll
        for (int ks = 0; ks < 8; ++ks) {
            u32 a[4];
            ldA_h<SXH>(s_hsH + (mrow + frow) * SXH + ks * 16 + 2 * fcol, a);
#pragma unroll
            for (int nt = 0; nt < 4; ++nt) {
                const uint2 b = g_mwh[2 * 4096 + (ks * 16 + ng * 4 + nt) * 32 + lane];
                mma16(acc[nt], a, b.x, b.y);
            }
        }
        const int rA = mrow + frow;
        const int iA = (r0 + rA) & 1023, iB = (r0 + rA + 8) & 1023;
        const float invA = 1.0f / ((iA + 1) < 5 ? (float)(iA + 1) : 5.0f);
        const float invB = 1.0f / ((iB + 1) < 5 ? (float)(iB + 1) : 5.0f);
#pragma unroll
        for (int nt = 0; nt < 4; ++nt) {
            const int gc = ng * 32 + nt * 8 + 2 * fcol;
            const float b20 = mb2[gc], b21 = mb2[gc + 1];
            *(u32*)(s_agH + rA * SXH + gc) =
                h2u(acc[nt].x * invA + b20, acc[nt].y * invA + b21);
            *(u32*)(s_agH + (rA + 8) * SXH + gc) =
                h2u(acc[nt].z * invB + b20, acc[nt].w * invB + b21);
        }
    }
    __syncthreads();

    // P4: uh
    {
        float4 acc[4];
#pragma unroll
        for (int nt = 0; nt < 4; ++nt) {
            const int gc = ng * 32 + nt * 8 + 2 * fcol;
            acc[nt] = make_float4(ub1[gc], ub1[gc + 1], ub1[gc], ub1[gc + 1]);
        }
#pragma unroll
        for (int ks = 0; ks < 8; ++ks) {
            u32 a[4];
            ldA_h<SXH>(s_hmtH + (4 + mrow + frow) * SXH + ks * 16 + 2 * fcol, a);
#pragma unroll
            for (int nt = 0; nt < 4; ++nt) {
                const uint2 b = g_mwh[3 * 4096 + (ks * 16 + ng * 4 + nt) * 32 + lane];
                mma16(acc[nt], a, b.x, b.y);
            }
        }
#pragma unroll
        for (int ks = 0; ks < 8; ++ks) {
            u32 a[4];
            ldA_h<SXH>(s_agH + (mrow + frow) * SXH + ks * 16 + 2 * fcol, a);
#pragma unroll
            for (int nt = 0; nt < 4; ++nt) {
                const uint2 b = g_mwh[4 * 4096 + (ks * 16 + ng * 4 + nt) * 32 + lane];
                mma16(acc[nt], a, b.x, b.y);
            }
        }
        __syncthreads();
        const int rA = mrow + frow;
#pragma unroll
        for (int nt = 0; nt < 4; ++nt) {
            const int gc = ng * 32 + nt * 8 + 2 * fcol;
            *(u32*)(s_uhH + rA * SXH + gc) =
                h2u(gelu_f(acc[nt].x), gelu_f(acc[nt].y));
            *(u32*)(s_uhH + (rA + 8) * SXH + gc) =
                h2u(gelu_f(acc[nt].z), gelu_f(acc[nt].w));
        }
    }
    __syncthreads();

    // P5: pre-LN = hmsg(fp32 gmem) + UH @ uw2 + ub2 -> s_pl
    {
        float4 acc[4];
#pragma unroll
        for (int nt = 0; nt < 4; ++nt) {
            const int gc = ng * 32 + nt * 8 + 2 * fcol;
            acc[nt] = make_float4(ub2[gc], ub2[gc + 1], ub2[gc], ub2[gc + 1]);
        }
#pragma unroll
        for (int ks = 0; ks < 8; ++ks) {
            u32 a[4];
            ldA_h<SXH>(s_uhH + (mrow + frow) * SXH + ks * 16 + 2 * fcol, a);
#pragma unroll
            for (int nt = 0; nt < 4; ++nt) {
                const uint2 b = g_mwh[5 * 4096 + (ks * 16 + ng * 4 + nt) * 32 + lane];
                mma16(acc[nt], a, b.x, b.y);
            }
        }
        const int rA = mrow + frow;
#pragma unroll
        for (int nt = 0; nt < 4; ++nt) {
            const int gc = ng * 32 + nt * 8 + 2 * fcol;
            const float2 h0 = *(const float2*)(hin + (r0 + rA) * Dm + gc);
            const float2 h1 = *(const float2*)(hin + (r0 + rA + 8) * Dm + gc);
            *(float2*)(s_pl + rA * SXL + gc) =
                make_float2(h0.x + acc[nt].x, h0.y + acc[nt].y);
            *(float2*)(s_pl + (rA + 8) * SXL + gc) =
                make_float2(h1.x + acc[nt].z, h1.y + acc[nt].w);
        }
    }
    __syncthreads();

    // P6: LN
#pragma unroll
    for (int rr = 0; rr < 4; ++rr) {
        const int r = wid * 4 + rr;
        const float4 v0 = *(const float4*)(s_pl + r * SXL + lane * 4);
        const float4 v = ln_f4(v0, lg, lb, lane);
        if (!last) {
            *(float4*)(hout + (r0 + r) * Dm + lane * 4) = v;
        } else {
            u32* dst = (u32*)(s_hmtH + (4 + r) * SXH) + lane * 2;
            dst[0] = h2u(v.x, v.y);
            dst[1] = h2u(v.z, v.w);
        }
    }

    // P7: bc (last round)
    if (last) {
        __syncthreads();
        float4 acc[4];
#pragma unroll
        for (int nt = 0; nt < 4; ++nt) {
            const int gc = ng * 32 + nt * 8 + 2 * fcol;
            acc[nt] = make_float4(bcb[gc], bcb[gc + 1], bcb[gc], bcb[gc + 1]);
        }
#pragma unroll
        for (int ks = 0; ks < 8; ++ks) {
            u32 a[4];
            ldA_h<SXH>(s_hmtH + (4 + mrow + frow) * SXH + ks * 16 + 2 * fcol, a);
#pragma unroll
            for (int nt = 0; nt < 4; ++nt) {
                const uint2 b = g_mwh[6 * 4096 + (ks * 16 + ng * 4 + nt) * 32 + lane];
                mma16(acc[nt], a, b.x, b.y);
            }
        }
        const int rA = r0 + mrow + frow;
#pragma unroll
        for (int nt = 0; nt < 4; ++nt) {
            const int gc = ng * 32 + nt * 8 + 2 * fcol;
            *(float2*)(g_bcb + rA * Dm + gc)       = make_float2(acc[nt].x, acc[nt].y);
            *(float2*)(g_bcb + (rA + 8) * Dm + gc) = make_float2(acc[nt].z, acc[nt].w);
        }
    }
}

// ============================================================
// K5: logits = LN(local + bc) @ head_w (fp16 MMA), 64 tok/block
// ============================================================
__global__ __launch_bounds__(256, 4) void k_head(
    const float* __restrict__ lg, const float* __restrict__ lb,
    float* __restrict__ out)
{
    __shared__ __half s_x[64 * SXH];
    const int tid = threadIdx.x, wid = tid >> 5, lane = tid & 31;
    const int gt0 = blockIdx.x * 64;
    const int frow = lane >> 2, fcol = lane & 3;

#pragma unroll
    for (int tt = 0; tt < 8; ++tt) {
        const int tl = wid * 8 + tt, gt = gt0 + tl;
        const u32* lp = (const u32*)(g_localh + gt * Dm) + lane * 2;
        const float2 l0 = uh2f(lp[0]), l1 = uh2f(lp[1]);
        const float4 bv = *(const float4*)(g_bcb + (gt >> 3) * Dm + lane * 4);
        const float4 h = make_float4(l0.x + bv.x, l0.y + bv.y, l1.x + bv.z, l1.y + bv.w);
        const float4 v = ln_f4(h, lg, lb, lane);
        u32* dst = (u32*)(s_x + tl * SXH) + lane * 2;
        dst[0] = h2u(v.x, v.y);
        dst[1] = h2u(v.z, v.w);
    }
    __syncthreads();

    const int mg = (wid >> 2) * 32;
    const int ng = (wid & 3);
    float4 acc[2][8];
#pragma unroll
    for (int mt = 0; mt < 2; ++mt)
#pragma unroll
        for (int nt = 0; nt < 8; ++nt) acc[mt][nt] = make_float4(0.f, 0.f, 0.f, 0.f);

#pragma unroll
    for (int ks = 0; ks < 8; ++ks) {
        u32 a[2][4];
#pragma unroll
        for (int mt = 0; mt < 2; ++mt)
            ldA_h<SXH>(s_x + (mg + mt * 16 + frow) * SXH + ks * 16 + 2 * fcol, a[mt]);
#pragma unroll
        for (int nt = 0; nt < 8; ++nt) {
            const uint2 b = g_hwh[(ks * 32 + ng * 8 + nt) * 32 + lane];
#pragma unroll
            for (int mt = 0; mt < 2; ++mt)
                mma16(acc[mt][nt], a[mt], b.x, b.y);
        }
    }

#pragma unroll
    for (int mt = 0; mt < 2; ++mt) {
        const int rg = gt0 + mg + mt * 16 + frow;
#pragma unroll
        for (int nt = 0; nt < 8; ++nt) {
            const int gc = ng * 64 + nt * 8 + 2 * fcol;
            *(float2*)(out + rg * Hm + gc)       = make_float2(acc[mt][nt].x, acc[mt][nt].y);
            *(float2*)(out + (rg + 8) * Hm + gc) = make_float2(acc[mt][nt].z, acc[mt][nt].w);
        }
    }
}

// ============================================================
extern "C" void kernel_launch(void* const* d_in, const int* in_sizes, int n_in,
                              void* d_out, int out_size) {
    const int*   x      = (const int*)  d_in[0];
    const float* emb    = (const float*)d_in[1];
    const float* pos    = (const float*)d_in[2];
    const float* lw1    = (const float*)d_in[3];
    const float* lb1    = (const float*)d_in[4];
    const float* lw2    = (const float*)d_in[5];
    const float* lb2    = (const float*)d_in[6];
    const float* lln_g  = (const float*)d_in[7];
    const float* lln_b  = (const float*)d_in[8];
    const float* pool_w = (const float*)d_in[9];
    const float* pool_b = (const float*)d_in[10];
    const float* msg_w1 = (const float*)d_in[11];
    const float* msg_b1 = (const float*)d_in[12];
    const float* msg_w2 = (const float*)d_in[13];
    const float* msg_b2 = (const float*)d_in[14];
    const float* upd_w1 = (const float*)d_in[15];
    const float* upd_b1 = (const float*)d_in[16];
    const float* upd_w2 = (const float*)d_in[17];
    const float* upd_b2 = (const float*)d_in[18];
    const float* mln_g  = (const float*)d_in[19];
    const float* mln_b  = (const float*)d_in[20];
    const float* bc_w   = (const float*)d_in[21];
    const float* bc_b   = (const float*)d_in[22];
    const float* fln_g  = (const float*)d_in[23];
    const float* fln_b  = (const float*)d_in[24];
    const float* head_w = (const float*)d_in[25];
    float* out = (float*)d_out;

    const int SMEM_LOCAL = (64 * SXH + 64 * SHH) * 2;         // 51200 B
    const int SMEM_MSG   = 136 * SXH * 2 + 32 * SXL * 4;      // 53888 B
    cudaFuncSetAttribute(k_local, cudaFuncAttributeMaxDynamicSharedMemorySize, SMEM_LOCAL);
    cudaFuncSetAttribute(k_msgf,  cudaFuncAttributeMaxDynamicSharedMemorySize, SMEM_MSG);

    k_pack_all<<<208, 256>>>(lw1, lw2, head_w, msg_w1, msg_w2, upd_w1, upd_w2, bc_w);

    k_local<<<NTOK / 64, 256, SMEM_LOCAL>>>(x, emb, pos, lb1, lb2,
                                            lln_g, lln_b, pool_w, pool_b);

    // rounds: A->B, B->A, A->(bc)  (last round writes g_bcb, skips hout)
    for (int r = 0; r < 3; ++r) {
        const int useA = (r % 2 == 0) ? 1 : 0;
        const int last = (r == 2) ? 1 : 0;
        k_msgf<<<ROWS / 32, 256, SMEM_MSG>>>(useA, last, msg_b1, msg_b2,
                                             upd_b1, upd_b2, mln_g, mln_b, bc_b);
    }

    k_head<<<NTOK / 64, 256>>>(fln_g, fln_b, out);
}

// round 17
// speedup vs baseline: 1.3407x; 1.3407x over previous
#include <cuda_runtime.h>
#include <cuda_fp16.h>

#define Dm 128
#define Hm 256
#define ROWS 16384   /* 16 * 1024 chunks */
#define NTOK 131072  /* 16 * 8192 tokens */
#define EPSf 1e-5f

typedef unsigned long long u64;
typedef unsigned int u32;

// ---- scratch (device globals; no allocation) ----
__device__ __half g_localh[NTOK * Dm]; // 32 MB (fp16 local)
__device__ float g_hA[ROWS * Dm];      // 8 MB
__device__ float g_hB[ROWS * Dm];      // 8 MB
__device__ float g_bcb[ROWS * Dm];     // 8 MB
// fp16 weight fragments (m16n8k16 B layout)
__device__ uint2 g_w1h[8 * 32 * 32];   // lw1 128x256
__device__ uint2 g_w2h[16 * 16 * 32];  // lw2 256x128
__device__ uint2 g_hwh[8 * 32 * 32];   // head_w 128x256
// fp16 128x128 msg mats: [0]=w1self [1]=w1nbr [2]=mw2 [3]=uw1a [4]=uw1b [5]=uw2 [6]=bc_w
__device__ uint2 g_mwh[7 * 4096];

// ---- packed f32x2 helpers (pool path) ----
__device__ __forceinline__ u64 pk2(float x, float y) {
    u64 r; asm("mov.b64 %0, {%1, %2};" : "=l"(r) : "f"(x), "f"(y)); return r;
}
__device__ __forceinline__ u64 dup_f(float a) {
    u64 r; asm("mov.b64 %0, {%1, %1};" : "=l"(r) : "f"(a)); return r;
}
__device__ __forceinline__ void fma2(u64& d, u64 a, u64 b) {
    asm("fma.rn.f32x2 %0, %1, %2, %0;" : "+l"(d) : "l"(a), "l"(b));
}
__device__ __forceinline__ float2 u2f(u64 v) {
    float2 r; asm("mov.b64 {%0, %1}, %2;" : "=f"(r.x), "=f"(r.y) : "l"(v)); return r;
}

// ---- fp16 helpers ----
__device__ __forceinline__ u32 h2u(float x, float y) {
    __half2 h = __floats2half2_rn(x, y);
    return *(u32*)&h;
}
__device__ __forceinline__ float2 uh2f(u32 v) {
    return __half22float2(*(__half2*)&v);
}

// mma.sync m16n8k16 f16 (fp32 accum)
__device__ __forceinline__ void mma16(float4& c, const u32 a[4], u32 b0, u32 b1) {
    asm volatile(
        "mma.sync.aligned.m16n8k16.row.col.f32.f16.f16.f32 "
        "{%0,%1,%2,%3}, {%4,%5,%6,%7}, {%8,%9}, {%0,%1,%2,%3};"
        : "+f"(c.x), "+f"(c.y), "+f"(c.z), "+f"(c.w)
        : "r"(a[0]), "r"(a[1]), "r"(a[2]), "r"(a[3]), "r"(b0), "r"(b1));
}

// fp16 A fragment: ap pre-offset to (row, ks*16 + 2*fcol), stride in halves
template<int STRIDE>
__device__ __forceinline__ void ldA_h(const __half* ap, u32 a[4]) {
    a[0] = *(const u32*)(ap);
    a[1] = *(const u32*)(ap + 8 * STRIDE);
    a[2] = *(const u32*)(ap + 8);
    a[3] = *(const u32*)(ap + 8 * STRIDE + 8);
}

__device__ __forceinline__ float wsum(float v) {
#pragma unroll
    for (int o = 16; o; o >>= 1) v += __shfl_xor_sync(0xffffffffu, v, o);
    return v;
}
__device__ __forceinline__ float gelu_f(float x) {
    return 0.5f * x * (1.0f + erff(x * 0.70710678118f));
}

__device__ __forceinline__ float4 ln_f4(float4 h, const float* __restrict__ g,
                                        const float* __restrict__ b, int lane) {
    const float mu = wsum(h.x + h.y + h.z + h.w) * (1.0f / 128.0f);
    const float a0 = h.x - mu, a1 = h.y - mu, a2 = h.z - mu, a3 = h.w - mu;
    const float var = wsum(a0 * a0 + a1 * a1 + a2 * a2 + a3 * a3) * (1.0f / 128.0f);
    const float rs = rsqrtf(var + EPSf);
    const int dd = lane * 4;
    const float4 gg = *(const float4*)(g + dd);
    const float4 bb = *(const float4*)(b + dd);
    return make_float4(a0 * rs * gg.x + bb.x, a1 * rs * gg.y + bb.y,
                       a2 * rs * gg.z + bb.z, a3 * rs * gg.w + bb.w);
}

// ---- scalar register-tiled GEMM accumulate (pool only) ----
template<int KDIM, int RPT, int NCP>
__device__ __forceinline__ void mm_acc(const float* __restrict__ s,
                                       const float* __restrict__ W, const int ldw,
                                       u64 acc[RPT][NCP]) {
#pragma unroll 2
    for (int d = 0; d < KDIM; d += 2) {
        u64 w0[NCP], w1[NCP];
        if constexpr (NCP >= 2) {
#pragma unroll
            for (int c = 0; c < NCP; c += 2) {
                const ulonglong2 t0 = *(const ulonglong2*)(W + d * ldw + c * 2);
                const ulonglong2 t1 = *(const ulonglong2*)(W + (d + 1) * ldw + c * 2);
                w0[c] = t0.x; w0[c + 1] = t0.y;
                w1[c] = t1.x; w1[c + 1] = t1.y;
            }
        } else {
            w0[0] = *(const u64*)(W + d * ldw);
            w1[0] = *(const u64*)(W + (d + 1) * ldw);
        }
#pragma unroll
        for (int r = 0; r < RPT; ++r) {
            const float2 a = *(const float2*)(s + r * KDIM + d);
            const u64 a0 = dup_f(a.x), a1 = dup_f(a.y);
#pragma unroll
            for (int c = 0; c < NCP; ++c) {
                fma2(acc[r][c], a0, w0[c]);
                fma2(acc[r][c], a1, w1[c]);
            }
        }
    }
}

// ============================================================
// K0: fused pack — everything to fp16 m16n8k16 B-fragments
// ============================================================
__device__ __forceinline__ void pack_one_h(const float* __restrict__ W,
                                           uint2* __restrict__ P,
                                           int N, int idx) {
    const int lane = idx & 31;
    const int t = idx >> 5;
    const int nt = t % (N / 8);
    const int ks = t / (N / 8);
    const int k0 = ks * 16 + 2 * (lane & 3);
    const int n = nt * 8 + (lane >> 2);
    uint2 r;
    r.x = h2u(W[k0 * N + n],       W[(k0 + 1) * N + n]);
    r.y = h2u(W[(k0 + 8) * N + n], W[(k0 + 9) * N + n]);
    P[idx] = r;
}

__global__ __launch_bounds__(256) void k_pack_all(
    const float* __restrict__ lw1, const float* __restrict__ lw2,
    const float* __restrict__ hw,  const float* __restrict__ mw1,
    const float* __restrict__ mw2, const float* __restrict__ uw1,
    const float* __restrict__ uw2, const float* __restrict__ bcw)
{
    const int b = blockIdx.x, tid = threadIdx.x;
    if      (b < 32)  pack_one_h(lw1, g_w1h, 256, b * 256 + tid);
    else if (b < 64)  pack_one_h(lw2, g_w2h, 128, (b - 32) * 256 + tid);
    else if (b < 96)  pack_one_h(hw,  g_hwh, 256, (b - 64) * 256 + tid);
    else if (b < 112) pack_one_h(mw1,           g_mwh + 0 * 4096, 128, (b - 96)  * 256 + tid);
    else if (b < 128) pack_one_h(mw1 + 16384,   g_mwh + 1 * 4096, 128, (b - 112) * 256 + tid);
    else if (b < 144) pack_one_h(mw2,           g_mwh + 2 * 4096, 128, (b - 128) * 256 + tid);
    else if (b < 160) pack_one_h(uw1,           g_mwh + 3 * 4096, 128, (b - 144) * 256 + tid);
    else if (b < 176) pack_one_h(uw1 + 16384,   g_mwh + 4 * 4096, 128, (b - 160) * 256 + tid);
    else if (b < 192) pack_one_h(uw2,           g_mwh + 5 * 4096, 128, (b - 176) * 256 + tid);
    else              pack_one_h(bcw,           g_mwh + 6 * 4096, 128, (b - 192) * 256 + tid);
}

// ============================================================
// K1: local = h + MLP2(LN(h)) + fused pool/summ  (fp16 MMA)
// 64 tokens/block, 256 threads, ~50KB smem, 3 CTAs/SM
// ============================================================
#define SXL 132   /* float stride */
#define SXH 136   /* half stride */
#define SHH 264   /* half stride for hidden */
__global__ __launch_bounds__(256, 3) void k_local(
    const int* __restrict__ x, const float* __restrict__ emb, const float* __restrict__ pos,
    const float* __restrict__ lb1, const float* __restrict__ lb2,
    const float* __restrict__ lng, const float* __restrict__ lnb,
    const float* __restrict__ pw, const float* __restrict__ pb)
{
    extern __shared__ char smc[];
    __half* s_x = (__half*)smc;                    // 64 x 136 halves
    __half* s_h = (__half*)(smc + 64 * SXH * 2);   // 64 x 264 halves
    const int tid = threadIdx.x, wid = tid >> 5, lane = tid & 31;
    const int gt0 = blockIdx.x * 64;
    const int frow = lane >> 2, fcol = lane & 3;

    // phase 1: LN per token -> fp16
#pragma unroll
    for (int tt = 0; tt < 8; ++tt) {
        const int tl = wid * 8 + tt, gt = gt0 + tl;
        const int xt = __ldg(x + gt);
        const float4 e = *(const float4*)(emb + xt * Dm + lane * 4);
        const float4 p = *(const float4*)(pos + (gt & 7) * Dm + lane * 4);
        const float4 h = make_float4(e.x + p.x, e.y + p.y, e.z + p.z, e.w + p.w);
        const float4 v = ln_f4(h, lng, lnb, lane);
        u32* dst = (u32*)(s_x + tl * SXH) + lane * 2;
        dst[0] = h2u(v.x, v.y);
        dst[1] = h2u(v.z, v.w);
    }
    __syncthreads();

    const int mg = (wid >> 2) * 32;
    const int ng = (wid & 3);

    // phase 2: hid = gelu(xln @ lw1 + b1)
    {
        float4 acc[2][8];
#pragma unroll
        for (int nt = 0; nt < 8; ++nt) {
            const int gc = ng * 64 + nt * 8 + 2 * fcol;
            const float b0 = lb1[gc], b1v = lb1[gc + 1];
#pragma unroll
            for (int mt = 0; mt < 2; ++mt) acc[mt][nt] = make_float4(b0, b1v, b0, b1v);
        }
#pragma unroll
        for (int ks = 0; ks < 8; ++ks) {
            u32 a[2][4];
#pragma unroll
            for (int mt = 0; mt < 2; ++mt)
                ldA_h<SXH>(s_x + (mg + mt * 16 + frow) * SXH + ks * 16 + 2 * fcol, a[mt]);
#pragma unroll
            for (int nt = 0; nt < 8; ++nt) {
                const uint2 b = g_w1h[(ks * 32 + ng * 8 + nt) * 32 + lane];
#pragma unroll
                for (int mt = 0; mt < 2; ++mt)
                    mma16(acc[mt][nt], a[mt], b.x, b.y);
            }
        }
#pragma unroll
        for (int mt = 0; mt < 2; ++mt) {
            const int rg = mg + mt * 16 + frow;
#pragma unroll
            for (int nt = 0; nt < 8; ++nt) {
                const int gc = ng * 64 + nt * 8 + 2 * fcol;
                *(u32*)(s_h + rg * SHH + gc) =
                    h2u(gelu_f(acc[mt][nt].x), gelu_f(acc[mt][nt].y));
                *(u32*)(s_h + (rg + 8) * SHH + gc) =
                    h2u(gelu_f(acc[mt][nt].z), gelu_f(acc[mt][nt].w));
            }
        }
    }
    __syncthreads();

    // phase 3: local = h + hid @ lw2 + b2 -> g_localh (fp16) and s_x (fp16)
    {
        float4 acc[2][4];
#pragma unroll
        for (int nt = 0; nt < 4; ++nt) {
            const int gc = ng * 32 + nt * 8 + 2 * fcol;
            const float b0 = lb2[gc], b1v = lb2[gc + 1];
#pragma unroll
            for (int mt = 0; mt < 2; ++mt) acc[mt][nt] = make_float4(b0, b1v, b0, b1v);
        }
#pragma unroll 4
        for (int ks = 0; ks < 16; ++ks) {
            u32 a[2][4];
#pragma unroll
            for (int mt = 0; mt < 2; ++mt)
                ldA_h<SHH>(s_h + (mg + mt * 16 + frow) * SHH + ks * 16 + 2 * fcol, a[mt]);
#pragma unroll
            for (int nt = 0; nt < 4; ++nt) {
                const uint2 b = g_w2h[(ks * 16 + ng * 4 + nt) * 32 + lane];
#pragma unroll
                for (int mt = 0; mt < 2; ++mt)
                    mma16(acc[mt][nt], a[mt], b.x, b.y);
            }
        }
#pragma unroll
        for (int mt = 0; mt < 2; ++mt) {
#pragma unroll
            for (int rr = 0; rr < 2; ++rr) {
                const int tl = mg + mt * 16 + frow + rr * 8;
                const int gt = gt0 + tl;
                const int xt = __ldg(x + gt);
#pragma unroll
                for (int nt = 0; nt < 4; ++nt) {
                    const int gc = ng * 32 + nt * 8 + 2 * fcol;
                    const float2 e = *(const float2*)(emb + xt * Dm + gc);
                    const float2 p = *(const float2*)(pos + (gt & 7) * Dm + gc);
                    const float cx = rr ? acc[mt][nt].z : acc[mt][nt].x;
                    const float cy = rr ? acc[mt][nt].w : acc[mt][nt].y;
                    const u32 oh = h2u(e.x + p.x + cx, e.y + p.y + cy);
                    *(u32*)(g_localh + gt * Dm + gc) = oh;
                    *(u32*)(s_x + tl * SXH + gc) = oh;
                }
            }
        }
    }
    __syncthreads();

    // phase 4: chunk means -> (float*)s_h[0:1024]
    float* s_m = (float*)s_h;
#pragma unroll
    for (int it = 0; it < 4; ++it) {
        const int idx = tid + it * 256;
        const int c = idx >> 7, dd = idx & 127;
        float s = 0.f;
#pragma unroll
        for (int t = 0; t < 8; ++t) s += __half2float(s_x[(c * 8 + t) * SXH + dd]);
        s_m[c * 128 + dd] = s * 0.125f;
    }
    __syncthreads();

    // phase 5: summ = mean @ pool_w + pool_b -> g_hA
    {
        const int j0 = lane * 4;
        u64 acc1[1][2];
        acc1[0][0] = pk2(pb[j0], pb[j0 + 1]);
        acc1[0][1] = pk2(pb[j0 + 2], pb[j0 + 3]);
        mm_acc<128, 1, 2>(s_m + wid * 128, pw + j0, 128, acc1);
        const float2 v0 = u2f(acc1[0][0]), v1 = u2f(acc1[0][1]);
        *(float4*)(g_hA + (blockIdx.x * 8 + wid) * Dm + j0) =
            make_float4(v0.x, v0.y, v1.x, v1.y);
    }
}

// ============================================================
// K2: FUSED msg round — fp16 MMA, fp32 residual from gmem
// (unchanged from 327us best)
// ============================================================
__global__ __launch_bounds__(256, 3) void k_msgf(
    int useA, int last,
    const float* __restrict__ mb1, const float* __restrict__ mb2,
    const float* __restrict__ ub1, const float* __restrict__ ub2,
    const float* __restrict__ lg, const float* __restrict__ lb,
    const float* __restrict__ bcb)
{
    const float* __restrict__ hin = useA ? g_hA : g_hB;
    float* __restrict__ hout = useA ? g_hB : g_hA;
    extern __shared__ char smc[];
    __half* s_hmtH = (__half*)smc;            // 36 rows
    __half* s_pnH  = s_hmtH + 36 * SXH;       // 36 rows
    __half* s_psH  = s_hmtH + 72 * SXH;       // 32 rows
    __half* s_hsH  = s_hmtH + 104 * SXH;      // 32 rows
    float*  s_pl   = (float*)(smc + 136 * SXH * 2);  // 32 x SXL fp32
    __half* s_agH  = s_pnH;
    __half* s_uhH  = s_psH;
    const int tid = threadIdx.x, wid = tid >> 5, lane = tid & 31;
    const int r0 = blockIdx.x * 32;
    const int frow = lane >> 2, fcol = lane & 3;
    const int ng = wid & 3;
    const int mgrp = wid >> 2;
    const int mrow = mgrp * 16;

    // P0
#pragma unroll
    for (int it = 0; it < 9; ++it) {
        const int idx = tid + it * 256;
        const int v = idx >> 6, jp = idx & 63;
        int row = r0 - 4 + v;
        row = row < 0 ? 0 : (row > ROWS - 1 ? ROWS - 1 : row);
        const float2 hv = *(const float2*)(hin + row * Dm + jp * 2);
        *((u32*)(s_hmtH + v * SXH) + jp) = h2u(hv.x, hv.y);
    }
    __syncthreads();

    // P1
    if (mgrp == 0) {
        float4 acc[2][4];
#pragma unroll
        for (int mt = 0; mt < 2; ++mt)
#pragma unroll
            for (int nt = 0; nt < 4; ++nt) acc[mt][nt] = make_float4(0.f, 0.f, 0.f, 0.f);
#pragma unroll
        for (int ks = 0; ks < 8; ++ks) {
            u32 a[2][4];
#pragma unroll
            for (int mt = 0; mt < 2; ++mt)
                ldA_h<SXH>(s_hmtH + (4 + mt * 16 + frow) * SXH + ks * 16 + 2 * fcol, a[mt]);
#pragma unroll
            for (int nt = 0; nt < 4; ++nt) {
                const uint2 b = g_mwh[0 * 4096 + (ks * 16 + ng * 4 + nt) * 32 + lane];
#pragma unroll
                for (int mt = 0; mt < 2; ++mt)
                    mma16(acc[mt][nt], a[mt], b.x, b.y);
            }
        }
#pragma unroll
        for (int mt = 0; mt < 2; ++mt) {
            const int r = mt * 16 + frow;
#pragma unroll
            for (int nt = 0; nt < 4; ++nt) {
                const int gc = ng * 32 + nt * 8 + 2 * fcol;
                *(u32*)(s_psH + r * SXH + gc)       = h2u(acc[mt][nt].x, acc[mt][nt].y);
                *(u32*)(s_psH + (r + 8) * SXH + gc) = h2u(acc[mt][nt].z, acc[mt][nt].w);
            }
        }
    } else {
        float4 acc[3][4];
#pragma unroll
        for (int mt = 0; mt < 3; ++mt)
#pragma unroll
            for (int nt = 0; nt < 4; ++nt) acc[mt][nt] = make_float4(0.f, 0.f, 0.f, 0.f);
        const int vb[3] = {0, 16, 20};
#pragma unroll
        for (int ks = 0; ks < 8; ++ks) {
            u32 a[3][4];
#pragma unroll
            for (int mt = 0; mt < 3; ++mt)
                ldA_h<SXH>(s_hmtH + (vb[mt] + frow) * SXH + ks * 16 + 2 * fcol, a[mt]);
#pragma unroll
            for (int nt = 0; nt < 4; ++nt) {
                const uint2 b = g_mwh[1 * 4096 + (ks * 16 + ng * 4 + nt) * 32 + lane];
#pragma unroll
                for (int mt = 0; mt < 3; ++mt)
                    mma16(acc[mt][nt], a[mt], b.x, b.y);
            }
        }
#pragma unroll
        for (int mt = 0; mt < 3; ++mt) {
            const int v = vb[mt] + frow;
#pragma unroll
            for (int nt = 0; nt < 4; ++nt) {
                const int gc = ng * 32 + nt * 8 + 2 * fcol;
                *(u32*)(s_pnH + v * SXH + gc)       = h2u(acc[mt][nt].x, acc[mt][nt].y);
                *(u32*)(s_pnH + (v + 8) * SXH + gc) = h2u(acc[mt][nt].z, acc[mt][nt].w);
            }
        }
    }
    __syncthreads();

    // P2: gelu-sum
#pragma unroll
    for (int it = 0; it < 8; ++it) {
        const int idx = tid + it * 256;
        const int r = idx >> 6, jp = idx & 63;
        const int i = (r0 + r) & 1023;
        const float2 b1v = *(const float2*)(mb1 + jp * 2);
        float2 ps = uh2f(*((const u32*)(s_psH + r * SXH) + jp));
        ps.x += b1v.x; ps.y += b1v.y;
        float a0 = 0.f, a1 = 0.f;
#pragma unroll
        for (int dd = 0; dd < 5; ++dd) {
            if (i >= dd) {
                const float2 pn = uh2f(*((const u32*)(s_pnH + (r + 4 - dd) * SXH) + jp));
                a0 += gelu_f(ps.x + pn.x);
                a1 += gelu_f(ps.y + pn.y);
            }
        }
        *((u32*)(s_hsH + r * SXH) + jp) = h2u(a0, a1);
    }
    __syncthreads();

    // P3: agg
    {
        float4 acc[4];
#pragma unroll
        for (int nt = 0; nt < 4; ++nt) acc[nt] = make_float4(0.f, 0.f, 0.f, 0.f);
#pragma unroll
        for (int ks = 0; ks < 8; ++ks) {
            u32 a[4];
            ldA_h<SXH>(s_hsH + (mrow + frow) * SXH + ks * 16 + 2 * fcol, a);
#pragma unroll
            for (int nt = 0; nt < 4; ++nt) {
                const uint2 b = g_mwh[2 * 4096 + (ks * 16 + ng * 4 + nt) * 32 + lane];
                mma16(acc[nt], a, b.x, b.y);
            }
        }
        const int rA = mrow + frow;
        const int iA = (r0 + rA) & 1023, iB = (r0 + rA + 8) & 1023;
        const float invA = 1.0f / ((iA + 1) < 5 ? (float)(iA + 1) : 5.0f);
        const float invB = 1.0f / ((iB + 1) < 5 ? (float)(iB + 1) : 5.0f);
#pragma unroll
        for (int nt = 0; nt < 4; ++nt) {
            const int gc = ng * 32 + nt * 8 + 2 * fcol;
            const float b20 = mb2[gc], b21 = mb2[gc + 1];
            *(u32*)(s_agH + rA * SXH + gc) =
                h2u(acc[nt].x * invA + b20, acc[nt].y * invA + b21);
            *(u32*)(s_agH + (rA + 8) * SXH + gc) =
                h2u(acc[nt].z * invB + b20, acc[nt].w * invB + b21);
        }
    }
    __syncthreads();

    // P4: uh
    {
        float4 acc[4];
#pragma unroll
        for (int nt = 0; nt < 4; ++nt) {
            const int gc = ng * 32 + nt * 8 + 2 * fcol;
            acc[nt] = make_float4(ub1[gc], ub1[gc + 1], ub1[gc], ub1[gc + 1]);
        }
#pragma unroll
        for (int ks = 0; ks < 8; ++ks) {
            u32 a[4];
            ldA_h<SXH>(s_hmtH + (4 + mrow + frow) * SXH + ks * 16 + 2 * fcol, a);
#pragma unroll
            for (int nt = 0; nt < 4; ++nt) {
                const uint2 b = g_mwh[3 * 4096 + (ks * 16 + ng * 4 + nt) * 32 + lane];
                mma16(acc[nt], a, b.x, b.y);
            }
        }
#pragma unroll
        for (int ks = 0; ks < 8; ++ks) {
            u32 a[4];
            ldA_h<SXH>(s_agH + (mrow + frow) * SXH + ks * 16 + 2 * fcol, a);
#pragma unroll
            for (int nt = 0; nt < 4; ++nt) {
                const uint2 b = g_mwh[4 * 4096 + (ks * 16 + ng * 4 + nt) * 32 + lane];
                mma16(acc[nt], a, b.x, b.y);
            }
        }
        __syncthreads();
        const int rA = mrow + frow;
#pragma unroll
        for (int nt = 0; nt < 4; ++nt) {
            const int gc = ng * 32 + nt * 8 + 2 * fcol;
            *(u32*)(s_uhH + rA * SXH + gc) =
                h2u(gelu_f(acc[nt].x), gelu_f(acc[nt].y));
            *(u32*)(s_uhH + (rA + 8) * SXH + gc) =
                h2u(gelu_f(acc[nt].z), gelu_f(acc[nt].w));
        }
    }
    __syncthreads();

    // P5: pre-LN = hmsg(fp32 gmem) + UH @ uw2 + ub2 -> s_pl
    {
        float4 acc[4];
#pragma unroll
        for (int nt = 0; nt < 4; ++nt) {
            const int gc = ng * 32 + nt * 8 + 2 * fcol;
            acc[nt] = make_float4(ub2[gc], ub2[gc + 1], ub2[gc], ub2[gc + 1]);
        }
#pragma unroll
        for (int ks = 0; ks < 8; ++ks) {
            u32 a[4];
            ldA_h<SXH>(s_uhH + (mrow + frow) * SXH + ks * 16 + 2 * fcol, a);
#pragma unroll
            for (int nt = 0; nt < 4; ++nt) {
                const uint2 b = g_mwh[5 * 4096 + (ks * 16 + ng * 4 + nt) * 32 + lane];
                mma16(acc[nt], a, b.x, b.y);
            }
        }
        const int rA = mrow + frow;
#pragma unroll
        for (int nt = 0; nt < 4; ++nt) {
            const int gc = ng * 32 + nt * 8 + 2 * fcol;
            const float2 h0 = *(const float2*)(hin + (r0 + rA) * Dm + gc);
            const float2 h1 = *(const float2*)(hin + (r0 + rA + 8) * Dm + gc);
            *(float2*)(s_pl + rA * SXL + gc) =
                make_float2(h0.x + acc[nt].x, h0.y + acc[nt].y);
            *(float2*)(s_pl + (rA + 8) * SXL + gc) =
                make_float2(h1.x + acc[nt].z, h1.y + acc[nt].w);
        }
    }
    __syncthreads();

    // P6: LN
#pragma unroll
    for (int rr = 0; rr < 4; ++rr) {
        const int r = wid * 4 + rr;
        const float4 v0 = *(const float4*)(s_pl + r * SXL + lane * 4);
        const float4 v = ln_f4(v0, lg, lb, lane);
        if (!last) {
            *(float4*)(hout + (r0 + r) * Dm + lane * 4) = v;
        } else {
            u32* dst = (u32*)(s_hmtH + (4 + r) * SXH) + lane * 2;
            dst[0] = h2u(v.x, v.y);
            dst[1] = h2u(v.z, v.w);
        }
    }

    // P7: bc (last round)
    if (last) {
        __syncthreads();
        float4 acc[4];
#pragma unroll
        for (int nt = 0; nt < 4; ++nt) {
            const int gc = ng * 32 + nt * 8 + 2 * fcol;
            acc[nt] = make_float4(bcb[gc], bcb[gc + 1], bcb[gc], bcb[gc + 1]);
        }
#pragma unroll
        for (int ks = 0; ks < 8; ++ks) {
            u32 a[4];
            ldA_h<SXH>(s_hmtH + (4 + mrow + frow) * SXH + ks * 16 + 2 * fcol, a);
#pragma unroll
            for (int nt = 0; nt < 4; ++nt) {
                const uint2 b = g_mwh[6 * 4096 + (ks * 16 + ng * 4 + nt) * 32 + lane];
                mma16(acc[nt], a, b.x, b.y);
            }
        }
        const int rA = r0 + mrow + frow;
#pragma unroll
        for (int nt = 0; nt < 4; ++nt) {
            const int gc = ng * 32 + nt * 8 + 2 * fcol;
            *(float2*)(g_bcb + rA * Dm + gc)       = make_float2(acc[nt].x, acc[nt].y);
            *(float2*)(g_bcb + (rA + 8) * Dm + gc) = make_float2(acc[nt].z, acc[nt].w);
        }
    }
}

// ============================================================
// K5: logits = LN(local + bc) @ head_w (fp16 MMA), 64 tok/block
// (no min-blocks cap: acc regs must stay in RF)
// ============================================================
__global__ __launch_bounds__(256) void k_head(
    const float* __restrict__ lg, const float* __restrict__ lb,
    float* __restrict__ out)
{
    __shared__ __half s_x[64 * SXH];
    const int tid = threadIdx.x, wid = tid >> 5, lane = tid & 31;
    const int gt0 = blockIdx.x * 64;
    const int frow = lane >> 2, fcol = lane & 3;

#pragma unroll
    for (int tt = 0; tt < 8; ++tt) {
        const int tl = wid * 8 + tt, gt = gt0 + tl;
        const u32* lp = (const u32*)(g_localh + gt * Dm) + lane * 2;
        const float2 l0 = uh2f(lp[0]), l1 = uh2f(lp[1]);
        const float4 bv = *(const float4*)(g_bcb + (gt >> 3) * Dm + lane * 4);
        const float4 h = make_float4(l0.x + bv.x, l0.y + bv.y, l1.x + bv.z, l1.y + bv.w);
        const float4 v = ln_f4(h, lg, lb, lane);
        u32* dst = (u32*)(s_x + tl * SXH) + lane * 2;
        dst[0] = h2u(v.x, v.y);
        dst[1] = h2u(v.z, v.w);
    }
    __syncthreads();

    const int mg = (wid >> 2) * 32;
    const int ng = (wid & 3);
    float4 acc[2][8];
#pragma unroll
    for (int mt = 0; mt < 2; ++mt)
#pragma unroll
        for (int nt = 0; nt < 8; ++nt) acc[mt][nt] = make_float4(0.f, 0.f, 0.f, 0.f);

#pragma unroll
    for (int ks = 0; ks < 8; ++ks) {
        u32 a[2][4];
#pragma unroll
        for (int mt = 0; mt < 2; ++mt)
            ldA_h<SXH>(s_x + (mg + mt * 16 + frow) * SXH + ks * 16 + 2 * fcol, a[mt]);
#pragma unroll
        for (int nt = 0; nt < 8; ++nt) {
            const uint2 b = g_hwh[(ks * 32 + ng * 8 + nt) * 32 + lane];
#pragma unroll
            for (int mt = 0; mt < 2; ++mt)
                mma16(acc[mt][nt], a[mt], b.x, b.y);
        }
    }

#pragma unroll
    for (int mt = 0; mt < 2; ++mt) {
        const int rg = gt0 + mg + mt * 16 + frow;
#pragma unroll
        for (int nt = 0; nt < 8; ++nt) {
            const int gc = ng * 64 + nt * 8 + 2 * fcol;
            *(float2*)(out + rg * Hm + gc)       = make_float2(acc[mt][nt].x, acc[mt][nt].y);
            *(float2*)(out + (rg + 8) * Hm + gc) = make_float2(acc[mt][nt].z, acc[mt][nt].w);
        }
    }
}

// ============================================================
extern "C" void kernel_launch(void* const* d_in, const int* in_sizes, int n_in,
                              void* d_out, int out_size) {
    const int*   x      = (const int*)  d_in[0];
    const float* emb    = (const float*)d_in[1];
    const float* pos    = (const float*)d_in[2];
    const float* lw1    = (const float*)d_in[3];
    const float* lb1    = (const float*)d_in[4];
    const float* lw2    = (const float*)d_in[5];
    const float* lb2    = (const float*)d_in[6];
    const float* lln_g  = (const float*)d_in[7];
    const float* lln_b  = (const float*)d_in[8];
    const float* pool_w = (const float*)d_in[9];
    const float* pool_b = (const float*)d_in[10];
    const float* msg_w1 = (const float*)d_in[11];
    const float* msg_b1 = (const float*)d_in[12];
    const float* msg_w2 = (const float*)d_in[13];
    const float* msg_b2 = (const float*)d_in[14];
    const float* upd_w1 = (const float*)d_in[15];
    const float* upd_b1 = (const float*)d_in[16];
    const float* upd_w2 = (const float*)d_in[17];
    const float* upd_b2 = (const float*)d_in[18];
    const float* mln_g  = (const float*)d_in[19];
    const float* mln_b  = (const float*)d_in[20];
    const float* bc_w   = (const float*)d_in[21];
    const float* bc_b   = (const float*)d_in[22];
    const float* fln_g  = (const float*)d_in[23];
    const float* fln_b  = (const float*)d_in[24];
    const float* head_w = (const float*)d_in[25];
    float* out = (float*)d_out;

    const int SMEM_LOCAL = (64 * SXH + 64 * SHH) * 2;         // 51200 B
    const int SMEM_MSG   = 136 * SXH * 2 + 32 * SXL * 4;      // 53888 B
    cudaFuncSetAttribute(k_local, cudaFuncAttributeMaxDynamicSharedMemorySize, SMEM_LOCAL);
    cudaFuncSetAttribute(k_msgf,  cudaFuncAttributeMaxDynamicSharedMemorySize, SMEM_MSG);

    k_pack_all<<<208, 256>>>(lw1, lw2, head_w, msg_w1, msg_w2, upd_w1, upd_w2, bc_w);

    k_local<<<NTOK / 64, 256, SMEM_LOCAL>>>(x, emb, pos, lb1, lb2,
                                            lln_g, lln_b, pool_w, pool_b);

    // rounds: A->B, B->A, A->(bc)  (last round writes g_bcb, skips hout)
    for (int r = 0; r < 3; ++r) {
        const int useA = (r % 2 == 0) ? 1 : 0;
        const int last = (r == 2) ? 1 : 0;
        k_msgf<<<ROWS / 32, 256, SMEM_MSG>>>(useA, last, msg_b1, msg_b2,
                                             upd_b1, upd_b2, mln_g, mln_b, bc_b);
    }

    k_head<<<NTOK / 64, 256>>>(fln_g, fln_b, out);
}